// round 14
// baseline (speedup 1.0000x reference)
#include <cuda_runtime.h>
#include <cuda_fp16.h>

#define B_    4
#define D_    96
#define N_    512
#define ATTN_ 256

// Scratch (device globals: no allocation in kernel_launch)
__device__ __half  g_G1h[B_ * N_ * ATTN_];   // [b][n][a]
__device__ __half  g_G2h[B_ * N_ * ATTN_];   // [b][m][a] (bg folded in)
__device__ __half2 g_wsh[ATTN_ / 2];         // packed Wa_w (written by proj blk 0)
__constant__ __half2 c_wsh[ATTN_ / 2];       // uniform-port reads, zero crossbar

union HU { unsigned u; __half2 h; };
__device__ __forceinline__ __half2 U2H(unsigned u) { HU t; t.u = u; return t.h; }
__device__ __forceinline__ unsigned H2U(__half2 h) { HU t; t.h = h; return t.u; }

__device__ __forceinline__ __half2 tanh2(__half2 x) {
    unsigned y;
    asm("tanh.approx.f16x2 %0, %1;" : "=r"(y) : "r"(H2U(x)));
    return U2H(y);
}

// ---------------------------------------------------------------------------
// Kernel 1: projections -> half outputs. grid = B*N/8 = 256 blocks, 256 thr.
// Block 0 additionally packs Wa_w into g_wsh (half2).
// ---------------------------------------------------------------------------
#define PR 8

__global__ __launch_bounds__(256) void proj_kernel(
        const float* __restrict__ x,
        const float* __restrict__ Wg1,
        const float* __restrict__ Wg2,
        const float* __restrict__ bg,
        const float* __restrict__ Wa_w) {
    extern __shared__ float psm[];
    float* W1s = psm;                     // [256][97]
    float* W2s = psm + 256 * 97;          // [256][97]
    float* xs  = psm + 2 * 256 * 97;      // [96][8]

    int blk = blockIdx.x;
    int b   = blk >> 6;
    int n0  = (blk & 63) << 3;
    int tid = threadIdx.x;

    if (blk == 0 && tid < ATTN_ / 2)
        g_wsh[tid] = __floats2half2_rn(Wa_w[2 * tid], Wa_w[2 * tid + 1]);

    for (int idx = tid; idx < 256 * 24; idx += 256) {
        int a = idx / 24;
        int c = idx - a * 24;
        float4 v1 = reinterpret_cast<const float4*>(Wg1)[idx];
        float4 v2 = reinterpret_cast<const float4*>(Wg2)[idx];
        float* d1 = W1s + a * 97 + c * 4;
        float* d2 = W2s + a * 97 + c * 4;
        d1[0] = v1.x; d1[1] = v1.y; d1[2] = v1.z; d1[3] = v1.w;
        d2[0] = v2.x; d2[1] = v2.y; d2[2] = v2.z; d2[3] = v2.w;
    }

    const float* xb = x + b * D_ * N_;
    for (int idx = tid; idx < D_ * PR; idx += 256) {
        int d = idx >> 3, j = idx & 7;
        xs[idx] = xb[d * N_ + n0 + j];
    }
    __syncthreads();

    int a = tid;
    float acc1[PR], acc2[PR];
#pragma unroll
    for (int j = 0; j < PR; j++) { acc1[j] = 0.f; acc2[j] = 0.f; }

    const float* w1 = W1s + a * 97;
    const float* w2 = W2s + a * 97;
#pragma unroll 4
    for (int d = 0; d < D_; d++) {
        float wa = w1[d];
        float wb = w2[d];
        float4 x0 = *reinterpret_cast<const float4*>(xs + d * 8);
        float4 x1 = *reinterpret_cast<const float4*>(xs + d * 8 + 4);
        acc1[0] = fmaf(x0.x, wa, acc1[0]); acc2[0] = fmaf(x0.x, wb, acc2[0]);
        acc1[1] = fmaf(x0.y, wa, acc1[1]); acc2[1] = fmaf(x0.y, wb, acc2[1]);
        acc1[2] = fmaf(x0.z, wa, acc1[2]); acc2[2] = fmaf(x0.z, wb, acc2[2]);
        acc1[3] = fmaf(x0.w, wa, acc1[3]); acc2[3] = fmaf(x0.w, wb, acc2[3]);
        acc1[4] = fmaf(x1.x, wa, acc1[4]); acc2[4] = fmaf(x1.x, wb, acc2[4]);
        acc1[5] = fmaf(x1.y, wa, acc1[5]); acc2[5] = fmaf(x1.y, wb, acc2[5]);
        acc1[6] = fmaf(x1.z, wa, acc1[6]); acc2[6] = fmaf(x1.z, wb, acc2[6]);
        acc1[7] = fmaf(x1.w, wa, acc1[7]); acc2[7] = fmaf(x1.w, wb, acc2[7]);
    }

    float bgv = bg[a];
#pragma unroll
    for (int j = 0; j < PR; j++) {
        int row = b * N_ + n0 + j;
        g_G1h[row * ATTN_ + a] = __float2half_rn(acc1[j]);
        g_G2h[row * ATTN_ + a] = __float2half_rn(acc2[j] + bgv);
    }
}

// ---------------------------------------------------------------------------
// Kernel 2: fused pairwise tanh (f16x2) + sigmoid + output matmul.
// grid = B * 64 * 2 = 512 blocks, 256 threads (8 warps).
// Warp w: n-pair p = w&3, a-half g = w>>2. Lane l <-> m (32-m tile).
// Register-lean inner loop: at most 3 uint4 quads live (C,W + A or Bv);
// s-loop unroll 2 to prevent load-buffer pipelining past the reg cap.
// z-exchange via pair-local named barriers (bar.sync p+1, 64); sigmoid
// split symmetrically: g=0 finalizes n=2p, g=1 finalizes n=2p+1.
// ---------------------------------------------------------------------------
#define NT 8
#define MT 32

// byte offsets into dynamic smem
#define OFFB_G1H  0                     // 8*256*2  = 4096
#define OFFB_ATT  4096                  // 8*33*4   = 1056
#define OFFB_ZB   5152                  // 2*4*32*4 = 1024
#define OFFB_G2H  6176                  // 32*264*2 = 16896
#define OFFB_XS   23072                 // 32*97*4  = 12416
#define SMEM_BYTES 35488

// single-n KSTEP: 1 HADD2 + 1 tanh2 + 1 HFMA2
#define K1(Av, Cv, Wv, Acc) {                                \
    __half2 t_ = tanh2(__hadd2(U2H(Av), U2H(Cv)));           \
    Acc = __hfma2(t_, U2H(Wv), Acc); }

#define PAIR_BAR() asm volatile("bar.sync %0, 64;" :: "r"(p + 1) : "memory")

__global__ __launch_bounds__(256, 4) void attn_kernel(
        const float* __restrict__ x,
        const float* __restrict__ Wa_b,
        const float* __restrict__ ba,
        float* __restrict__ out) {
    extern __shared__ char smc[];
    __half* G1s   = reinterpret_cast<__half*>(smc + OFFB_G1H);   // [n][256]
    float*  att_s = reinterpret_cast<float*>(smc + OFFB_ATT);    // [n][33]
    float*  zb0   = reinterpret_cast<float*>(smc + OFFB_ZB);     // [4][32]: g=1's n0 partial
    float*  zb1   = zb0 + 128;                                   // [4][32]: g=0's n1 partial
    __half* G2s   = reinterpret_cast<__half*>(smc + OFFB_G2H);   // [m][264]
    float*  xs    = reinterpret_cast<float*>(smc + OFFB_XS);     // [m][97]

    int blk  = blockIdx.x;         // 512 = B * 64 * 2
    int b    = blk >> 7;
    int r    = blk & 127;
    int n0   = (r >> 1) << 3;
    int mbase = (r & 1) << 8;
    int tid  = threadIdx.x;
    int w    = tid >> 5, l = tid & 31;
    int p    = w & 3;              // n-pair 0..3
    int g    = w >> 2;             // a-half 0/1

    // G1 tile: 8*256 halves = 4096 B = 256 uint4, one per thread.
    {
        const uint4* src = reinterpret_cast<const uint4*>(
                               g_G1h + (b * N_ + n0) * ATTN_);
        reinterpret_cast<uint4*>(smc + OFFB_G1H)[tid] = src[tid];
    }
    float bias = Wa_b[0] + ba[0];

    const float* xb = x + b * D_ * N_;
    float o00 = 0.f, o01 = 0.f, o02 = 0.f;
    float o10 = 0.f, o11 = 0.f, o12 = 0.f;

    const __half* g1r0 = G1s + (p << 1) * ATTN_;
    const __half* g1r1 = g1r0 + ATTN_;
    const __half* g2l  = G2s + l * 264;
    const float*  ar0  = att_s + (p << 1) * 33;
    const uint4*  wq   = reinterpret_cast<const uint4*>(c_wsh);

    for (int mt = 0; mt < 8; mt++) {
        int m0 = mbase + mt * MT;
        __syncthreads();  // A: prev tile's epilogue readers done

        // Stage G2 tile [m][264] halves (rows 528B = 33x16B, conflict-free)
        {
            const uint4* g2g = reinterpret_cast<const uint4*>(
                                   g_G2h + (b * N_ + m0) * ATTN_);
            for (int idx = tid; idx < 1024; idx += 256) {
                int m = idx >> 5, c = idx & 31;
                *(reinterpret_cast<uint4*>(G2s + m * 264) + c) = g2g[idx];
            }
        }
        // x tile [m][97] f32
        for (int idx = tid; idx < MT * D_; idx += 256) {
            int m = idx & 31, d = idx >> 5;
            xs[m * 97 + d] = xb[d * N_ + m0 + m];
        }
        __syncthreads();  // B: tiles staged

        // Hot loop: this warp's 128-a half, both n of the pair, half2 math.
        // Register-lean: consume A fully before loading Bv.
        float zf0 = 0.f, zf1 = 0.f;
#pragma unroll 1
        for (int c = 0; c < 4; c++) {
            int ah = (g << 7) + (c << 5);            // half-index base, 32 a
            __half2 a00 = __float2half2_rn(0.f), a01 = a00;
            __half2 a10 = a00, a11 = a00;
#pragma unroll 2
            for (int s = 0; s < 4; s++) {
                int off = ah + (s << 3);             // 8 a
                uint4 C = *reinterpret_cast<const uint4*>(g2l + off);
                uint4 W = wq[off >> 3];              // const port
                {
                    uint4 A = *reinterpret_cast<const uint4*>(g1r0 + off);
                    K1(A.x, C.x, W.x, a00);
                    K1(A.y, C.y, W.y, a01);
                    K1(A.z, C.z, W.z, a00);
                    K1(A.w, C.w, W.w, a01);
                }
                {
                    uint4 Bv = *reinterpret_cast<const uint4*>(g1r1 + off);
                    K1(Bv.x, C.x, W.x, a10);
                    K1(Bv.y, C.y, W.y, a11);
                    K1(Bv.z, C.z, W.z, a10);
                    K1(Bv.w, C.w, W.w, a11);
                }
            }
            // Flush to fp32 (bounds f16 accumulation error)
            float2 f;
            f = __half22float2(a00); zf0 += f.x + f.y;
            f = __half22float2(a01); zf0 += f.x + f.y;
            f = __half22float2(a10); zf1 += f.x + f.y;
            f = __half22float2(a11); zf1 += f.x + f.y;
        }

        // Symmetric pair exchange: g=0 finalizes n=2p, g=1 finalizes n=2p+1.
        if (g == 0) zb1[p * 32 + l] = zf1;    // hand n1 partial to g=1
        else        zb0[p * 32 + l] = zf0;    // hand n0 partial to g=0
        PAIR_BAR();  // C': pair-local

        if (g == 0) {
            float z = zf0 + zb0[p * 32 + l];
            att_s[(p << 1) * 33 + l] = 1.0f / (1.0f + __expf(-(z + bias)));
        } else {
            float z = zf1 + zb1[p * 32 + l];
            att_s[((p << 1) + 1) * 33 + l] = 1.0f / (1.0f + __expf(-(z + bias)));
        }
        PAIR_BAR();  // D': pair-local, att rows of this pair visible

        // Epilogue: group g covers m in [16g,16g+16); paired n shares xs loads.
#pragma unroll 4
        for (int mm = 0; mm < 16; mm++) {
            int mli = (g << 4) + mm;
            float av0 = ar0[mli];
            float av1 = ar0[33 + mli];
            const float* xr = xs + mli * 97;
            float x0 = xr[l];
            float x1 = xr[l + 32];
            float x2 = xr[l + 64];
            o00 = fmaf(av0, x0, o00);
            o01 = fmaf(av0, x1, o01);
            o02 = fmaf(av0, x2, o02);
            o10 = fmaf(av1, x0, o10);
            o11 = fmaf(av1, x1, o11);
            o12 = fmaf(av1, x2, o12);
        }
    }

    // Combine m-halves and a-split warps (atomics into pre-zeroed out).
    float* op0 = out + (b * N_ + n0 + (p << 1)) * D_;
    float* op1 = op0 + D_;
    atomicAdd(op0 + l,      o00);
    atomicAdd(op0 + l + 32, o01);
    atomicAdd(op0 + l + 64, o02);
    atomicAdd(op1 + l,      o10);
    atomicAdd(op1 + l + 32, o11);
    atomicAdd(op1 + l + 64, o12);
}

// ---------------------------------------------------------------------------
extern "C" void kernel_launch(void* const* d_in, const int* in_sizes, int n_in,
                              void* d_out, int out_size) {
    const float* x    = (const float*)d_in[0];
    const float* Wg1  = (const float*)d_in[1];
    const float* Wg2  = (const float*)d_in[2];
    const float* bg   = (const float*)d_in[3];
    const float* Wa_w = (const float*)d_in[4];
    const float* Wa_b = (const float*)d_in[5];
    const float* ba   = (const float*)d_in[6];
    float* out = (float*)d_out;

    // out receives atomicAdd partials: zero it first.
    cudaMemsetAsync(d_out, 0, (size_t)out_size * sizeof(float));

    int proj_smem = (2 * 256 * 97 + D_ * PR) * (int)sizeof(float);
    cudaFuncSetAttribute(proj_kernel,
                         cudaFuncAttributeMaxDynamicSharedMemorySize, proj_smem);
    proj_kernel<<<(B_ * N_) / PR, 256, proj_smem>>>(x, Wg1, Wg2, bg, Wa_w);

    // Packed half2 weights -> constant memory (in-stream after proj; D2D).
    void* wsp = nullptr;
    cudaGetSymbolAddress(&wsp, g_wsh);
    cudaMemcpyToSymbolAsync(c_wsh, wsp, (ATTN_ / 2) * sizeof(__half2), 0,
                            cudaMemcpyDeviceToDevice);

    attn_kernel<<<B_ * (N_ / NT) * 2, 256, SMEM_BYTES>>>(x, Wa_b, ba, out);
}

// round 16
// speedup vs baseline: 1.0191x; 1.0191x over previous
#include <cuda_runtime.h>
#include <cuda_fp16.h>

#define B_    4
#define D_    96
#define N_    512
#define ATTN_ 256

// Scratch (device globals: no allocation in kernel_launch)
__device__ __half  g_G1h[B_ * N_ * ATTN_];   // [b][n][a]
__device__ __half  g_G2h[B_ * N_ * ATTN_];   // [b][m][a] (bg folded in)
__device__ __half2 g_wsh[ATTN_ / 2];         // packed Wa_w (written by proj blk 0)
__constant__ __half2 c_wsh[ATTN_ / 2];       // uniform-port reads, zero crossbar

union HU { unsigned u; __half2 h; };
__device__ __forceinline__ __half2 U2H(unsigned u) { HU t; t.u = u; return t.h; }
__device__ __forceinline__ unsigned H2U(__half2 h) { HU t; t.h = h; return t.u; }

__device__ __forceinline__ __half2 tanh2(__half2 x) {
    unsigned y;
    asm("tanh.approx.f16x2 %0, %1;" : "=r"(y) : "r"(H2U(x)));
    return U2H(y);
}

// ---------------------------------------------------------------------------
// Kernel 1: projections -> half outputs. grid = B*N/8 = 256 blocks, 256 thr.
// Also zeroes the output buffer (out = 196608 floats = 49152 float4; ONE
// guarded float4 per thread) and block 0 packs Wa_w into g_wsh (half2).
// ---------------------------------------------------------------------------
#define PR 8
#define OUT_F4 ((B_ * N_ * D_) / 4)   // 49152 float4

__global__ __launch_bounds__(256) void proj_kernel(
        const float* __restrict__ x,
        const float* __restrict__ Wg1,
        const float* __restrict__ Wg2,
        const float* __restrict__ bg,
        const float* __restrict__ Wa_w,
        float* __restrict__ out) {
    extern __shared__ float psm[];
    float* W1s = psm;                     // [256][97]
    float* W2s = psm + 256 * 97;          // [256][97]
    float* xs  = psm + 2 * 256 * 97;      // [96][8]

    int blk = blockIdx.x;
    int b   = blk >> 6;
    int n0  = (blk & 63) << 3;
    int tid = threadIdx.x;

    // Zero the output (out receives atomicAdd partials in attn_kernel).
    {
        int base = blk * 256 + tid;                 // 65536 threads total
        if (base < OUT_F4)
            reinterpret_cast<float4*>(out)[base] = make_float4(0.f, 0.f, 0.f, 0.f);
    }

    if (blk == 0 && tid < ATTN_ / 2)
        g_wsh[tid] = __floats2half2_rn(Wa_w[2 * tid], Wa_w[2 * tid + 1]);

    for (int idx = tid; idx < 256 * 24; idx += 256) {
        int a = idx / 24;
        int c = idx - a * 24;
        float4 v1 = reinterpret_cast<const float4*>(Wg1)[idx];
        float4 v2 = reinterpret_cast<const float4*>(Wg2)[idx];
        float* d1 = W1s + a * 97 + c * 4;
        float* d2 = W2s + a * 97 + c * 4;
        d1[0] = v1.x; d1[1] = v1.y; d1[2] = v1.z; d1[3] = v1.w;
        d2[0] = v2.x; d2[1] = v2.y; d2[2] = v2.z; d2[3] = v2.w;
    }

    const float* xb = x + b * D_ * N_;
    for (int idx = tid; idx < D_ * PR; idx += 256) {
        int d = idx >> 3, j = idx & 7;
        xs[idx] = xb[d * N_ + n0 + j];
    }
    __syncthreads();

    int a = tid;
    float acc1[PR], acc2[PR];
#pragma unroll
    for (int j = 0; j < PR; j++) { acc1[j] = 0.f; acc2[j] = 0.f; }

    const float* w1 = W1s + a * 97;
    const float* w2 = W2s + a * 97;
#pragma unroll 4
    for (int d = 0; d < D_; d++) {
        float wa = w1[d];
        float wb = w2[d];
        float4 x0 = *reinterpret_cast<const float4*>(xs + d * 8);
        float4 x1 = *reinterpret_cast<const float4*>(xs + d * 8 + 4);
        acc1[0] = fmaf(x0.x, wa, acc1[0]); acc2[0] = fmaf(x0.x, wb, acc2[0]);
        acc1[1] = fmaf(x0.y, wa, acc1[1]); acc2[1] = fmaf(x0.y, wb, acc2[1]);
        acc1[2] = fmaf(x0.z, wa, acc1[2]); acc2[2] = fmaf(x0.z, wb, acc2[2]);
        acc1[3] = fmaf(x0.w, wa, acc1[3]); acc2[3] = fmaf(x0.w, wb, acc2[3]);
        acc1[4] = fmaf(x1.x, wa, acc1[4]); acc2[4] = fmaf(x1.x, wb, acc2[4]);
        acc1[5] = fmaf(x1.y, wa, acc1[5]); acc2[5] = fmaf(x1.y, wb, acc2[5]);
        acc1[6] = fmaf(x1.z, wa, acc1[6]); acc2[6] = fmaf(x1.z, wb, acc2[6]);
        acc1[7] = fmaf(x1.w, wa, acc1[7]); acc2[7] = fmaf(x1.w, wb, acc2[7]);
    }

    float bgv = bg[a];
#pragma unroll
    for (int j = 0; j < PR; j++) {
        int row = b * N_ + n0 + j;
        g_G1h[row * ATTN_ + a] = __float2half_rn(acc1[j]);
        g_G2h[row * ATTN_ + a] = __float2half_rn(acc2[j] + bgv);
    }
}

// ---------------------------------------------------------------------------
// Kernel 2: fused pairwise tanh (f16x2) + sigmoid + output matmul.
// grid = B * 128 * 2 = 1024 blocks, 128 threads (4 warps), 7 blocks/SM
// (single wave: 148*7 = 1036 >= 1024; busiest/avg imbalance = 1.01 vs the
// old 512-block 1.16). n-tile = 4 rows, m-half = 256 (8 tiles of 32).
// Warp w: n-pair p = w&1, a-half g = w>>1. Lane l <-> m within tile.
// xs stored as HALF, transposed [d][34] (17*l banking -> conflict-free).
// ---------------------------------------------------------------------------
#define MT 32

// byte offsets into dynamic smem
#define OFFB_G1H  0                     // 4*256*2  = 2048
#define OFFB_ATT  2048                  // 4*33*4   = 528
#define OFFB_ZB   2576                  // 2*2*32*4 = 512
#define OFFB_G2H  3088                  // 32*264*2 = 16896
#define OFFB_XS   19984                 // 96*34*2  = 6528
#define SMEM_BYTES 26512                // 7 blocks/SM

// single-n KSTEP: 1 HADD2 + 1 tanh2 + 1 HFMA2
#define K1(Av, Cv, Wv, Acc) {                                \
    __half2 t_ = tanh2(__hadd2(U2H(Av), U2H(Cv)));           \
    Acc = __hfma2(t_, U2H(Wv), Acc); }

#define PAIR_BAR() asm volatile("bar.sync %0, 64;" :: "r"(p + 1) : "memory")

__global__ __launch_bounds__(128, 7) void attn_kernel(
        const float* __restrict__ x,
        const float* __restrict__ Wa_b,
        const float* __restrict__ ba,
        float* __restrict__ out) {
    extern __shared__ char smc[];
    __half* G1s   = reinterpret_cast<__half*>(smc + OFFB_G1H);   // [4][256]
    float*  att_s = reinterpret_cast<float*>(smc + OFFB_ATT);    // [4][33]
    float*  zb0   = reinterpret_cast<float*>(smc + OFFB_ZB);     // [2][32]
    float*  zb1   = zb0 + 64;                                    // [2][32]
    __half* G2s   = reinterpret_cast<__half*>(smc + OFFB_G2H);   // [m][264]
    __half* xst   = reinterpret_cast<__half*>(smc + OFFB_XS);    // [d][34]

    int blk  = blockIdx.x;         // 1024 = B * 128 * 2
    int b    = blk >> 8;
    int r    = blk & 255;
    int n0   = (r >> 1) << 2;      // 4 n-rows per block
    int mbase = (r & 1) << 8;      // m-half: 0 or 256
    int tid  = threadIdx.x;
    int w    = tid >> 5, l = tid & 31;
    int p    = w & 1;              // n-pair 0..1
    int g    = w >> 1;             // a-half 0/1

    // G1 tile: 4*256 halves = 2048 B = 128 uint4, one per thread.
    {
        const uint4* src = reinterpret_cast<const uint4*>(
                               g_G1h + (b * N_ + n0) * ATTN_);
        reinterpret_cast<uint4*>(smc + OFFB_G1H)[tid] = src[tid];
    }
    float bias = Wa_b[0] + ba[0];

    const float* xb = x + b * D_ * N_;
    float o00 = 0.f, o01 = 0.f, o02 = 0.f;
    float o10 = 0.f, o11 = 0.f, o12 = 0.f;

    const __half* g1r0 = G1s + (p << 1) * ATTN_;
    const __half* g1r1 = g1r0 + ATTN_;
    const __half* g2l  = G2s + l * 264;
    const float*  ar0  = att_s + (p << 1) * 33;
    const uint4*  wq   = reinterpret_cast<const uint4*>(c_wsh);

    for (int mt = 0; mt < 8; mt++) {
        int m0 = mbase + mt * MT;
        __syncthreads();  // A: prev tile's epilogue readers done

        // Stage G2 tile [m][264] halves (rows 528B; LDS.128 phases CF)
        {
            const uint4* g2g = reinterpret_cast<const uint4*>(
                                   g_G2h + (b * N_ + m0) * ATTN_);
            for (int idx = tid; idx < 1024; idx += 128) {
                int m = idx >> 5, c = idx & 31;
                *(reinterpret_cast<uint4*>(G2s + m * 264) + c) = g2g[idx];
            }
        }
        // x tile, transposed to [d][34] half (global coalesced over m)
        for (int idx = tid; idx < D_ * MT; idx += 128) {
            int m = idx & 31, d = idx >> 5;
            xst[d * 34 + m] = __float2half_rn(xb[d * N_ + m0 + m]);
        }
        __syncthreads();  // B: tiles staged

        // Hot loop: this warp's 128-a half, both n of the pair, half2 math.
        float zf0 = 0.f, zf1 = 0.f;
#pragma unroll 1
        for (int c = 0; c < 4; c++) {
            int ah = (g << 7) + (c << 5);            // half-index base, 32 a
            __half2 a00 = __float2half2_rn(0.f), a01 = a00;
            __half2 a10 = a00, a11 = a00;
#pragma unroll 2
            for (int s = 0; s < 4; s++) {
                int off = ah + (s << 3);             // 8 a
                uint4 C = *reinterpret_cast<const uint4*>(g2l + off);
                uint4 W = wq[off >> 3];              // const port
                {
                    uint4 A = *reinterpret_cast<const uint4*>(g1r0 + off);
                    K1(A.x, C.x, W.x, a00);
                    K1(A.y, C.y, W.y, a01);
                    K1(A.z, C.z, W.z, a00);
                    K1(A.w, C.w, W.w, a01);
                }
                {
                    uint4 Bv = *reinterpret_cast<const uint4*>(g1r1 + off);
                    K1(Bv.x, C.x, W.x, a10);
                    K1(Bv.y, C.y, W.y, a11);
                    K1(Bv.z, C.z, W.z, a10);
                    K1(Bv.w, C.w, W.w, a11);
                }
            }
            // Flush to fp32 (bounds f16 accumulation error)
            float2 f;
            f = __half22float2(a00); zf0 += f.x + f.y;
            f = __half22float2(a01); zf0 += f.x + f.y;
            f = __half22float2(a10); zf1 += f.x + f.y;
            f = __half22float2(a11); zf1 += f.x + f.y;
        }

        // Symmetric pair exchange: g=0 finalizes n=2p, g=1 finalizes n=2p+1.
        if (g == 0) zb1[p * 32 + l] = zf1;    // hand n1 partial to g=1
        else        zb0[p * 32 + l] = zf0;    // hand n0 partial to g=0
        PAIR_BAR();  // C': pair-local

        if (g == 0) {
            float z = zf0 + zb0[p * 32 + l];
            att_s[(p << 1) * 33 + l] = 1.0f / (1.0f + __expf(-(z + bias)));
        } else {
            float z = zf1 + zb1[p * 32 + l];
            att_s[((p << 1) + 1) * 33 + l] = 1.0f / (1.0f + __expf(-(z + bias)));
        }
        PAIR_BAR();  // D': pair-local, att rows of this pair visible

        // Epilogue: group g covers m in [16g,16g+16); paired n shares x loads.
        const __half* x0p = xst + l * 34;
        const __half* x1p = xst + (l + 32) * 34;
        const __half* x2p = xst + (l + 64) * 34;
#pragma unroll 4
        for (int mm = 0; mm < 16; mm++) {
            int mli = (g << 4) + mm;
            float av0 = ar0[mli];
            float av1 = ar0[33 + mli];
            float x0 = __half2float(x0p[mli]);
            float x1 = __half2float(x1p[mli]);
            float x2 = __half2float(x2p[mli]);
            o00 = fmaf(av0, x0, o00);
            o01 = fmaf(av0, x1, o01);
            o02 = fmaf(av0, x2, o02);
            o10 = fmaf(av1, x0, o10);
            o11 = fmaf(av1, x1, o11);
            o12 = fmaf(av1, x2, o12);
        }
    }

    // Combine m-halves and a-split warps (atomics into pre-zeroed out).
    float* op0 = out + (b * N_ + n0 + (p << 1)) * D_;
    float* op1 = op0 + D_;
    atomicAdd(op0 + l,      o00);
    atomicAdd(op0 + l + 32, o01);
    atomicAdd(op0 + l + 64, o02);
    atomicAdd(op1 + l,      o10);
    atomicAdd(op1 + l + 32, o11);
    atomicAdd(op1 + l + 64, o12);
}

// ---------------------------------------------------------------------------
extern "C" void kernel_launch(void* const* d_in, const int* in_sizes, int n_in,
                              void* d_out, int out_size) {
    const float* x    = (const float*)d_in[0];
    const float* Wg1  = (const float*)d_in[1];
    const float* Wg2  = (const float*)d_in[2];
    const float* bg   = (const float*)d_in[3];
    const float* Wa_w = (const float*)d_in[4];
    const float* Wa_b = (const float*)d_in[5];
    const float* ba   = (const float*)d_in[6];
    float* out = (float*)d_out;

    int proj_smem = (2 * 256 * 97 + D_ * PR) * (int)sizeof(float);
    cudaFuncSetAttribute(proj_kernel,
                         cudaFuncAttributeMaxDynamicSharedMemorySize, proj_smem);
    proj_kernel<<<(B_ * N_) / PR, 256, proj_smem>>>(x, Wg1, Wg2, bg, Wa_w, out);

    // Packed half2 weights -> constant memory (in-stream after proj; D2D).
    void* wsp = nullptr;
    cudaGetSymbolAddress(&wsp, g_wsh);
    cudaMemcpyToSymbolAsync(c_wsh, wsp, (ATTN_ / 2) * sizeof(__half2), 0,
                            cudaMemcpyDeviceToDevice);

    attn_kernel<<<B_ * 128 * 2, 128, SMEM_BYTES>>>(x, Wa_b, ba, out);
}

// round 17
// speedup vs baseline: 1.0895x; 1.0691x over previous
#include <cuda_runtime.h>
#include <cuda_fp16.h>

#define B_    4
#define D_    96
#define N_    512
#define ATTN_ 256

// Scratch (device globals: no allocation in kernel_launch)
__device__ __half  g_G1h[B_ * N_ * ATTN_];   // [b][n][a]
__device__ __half  g_G2h[B_ * N_ * ATTN_];   // [b][m][a] (bg folded in)
__device__ __half2 g_wsh[ATTN_ / 2];         // packed Wa_w (written by proj blk 0)
__constant__ __half2 c_wsh[ATTN_ / 2];       // uniform-port reads, zero crossbar

union HU { unsigned u; __half2 h; };
__device__ __forceinline__ __half2 U2H(unsigned u) { HU t; t.u = u; return t.h; }
__device__ __forceinline__ unsigned H2U(__half2 h) { HU t; t.h = h; return t.u; }

__device__ __forceinline__ __half2 tanh2(__half2 x) {
    unsigned y;
    asm("tanh.approx.f16x2 %0, %1;" : "=r"(y) : "r"(H2U(x)));
    return U2H(y);
}

// ---------------------------------------------------------------------------
// Kernel 1: projections -> half outputs. grid = B*N/8 = 256 blocks, 256 thr.
// Also zeroes out (196608 floats = 49152 float4, one guarded f4/thread) and
// block 0 packs Wa_w into g_wsh.
// ---------------------------------------------------------------------------
#define PR 8
#define OUT_F4 ((B_ * N_ * D_) / 4)   // 49152

__global__ __launch_bounds__(256) void proj_kernel(
        const float* __restrict__ x,
        const float* __restrict__ Wg1,
        const float* __restrict__ Wg2,
        const float* __restrict__ bg,
        const float* __restrict__ Wa_w,
        float* __restrict__ out) {
    extern __shared__ float psm[];
    float* W1s = psm;                     // [256][97]
    float* W2s = psm + 256 * 97;          // [256][97]
    float* xs  = psm + 2 * 256 * 97;      // [96][8]

    int blk = blockIdx.x;
    int b   = blk >> 6;
    int n0  = (blk & 63) << 3;
    int tid = threadIdx.x;

    // Zero the output (receives atomicAdd partials in attn_kernel).
    {
        int base = blk * 256 + tid;
        if (base < OUT_F4)
            reinterpret_cast<float4*>(out)[base] = make_float4(0.f, 0.f, 0.f, 0.f);
    }

    if (blk == 0 && tid < ATTN_ / 2)
        g_wsh[tid] = __floats2half2_rn(Wa_w[2 * tid], Wa_w[2 * tid + 1]);

    for (int idx = tid; idx < 256 * 24; idx += 256) {
        int a = idx / 24;
        int c = idx - a * 24;
        float4 v1 = reinterpret_cast<const float4*>(Wg1)[idx];
        float4 v2 = reinterpret_cast<const float4*>(Wg2)[idx];
        float* d1 = W1s + a * 97 + c * 4;
        float* d2 = W2s + a * 97 + c * 4;
        d1[0] = v1.x; d1[1] = v1.y; d1[2] = v1.z; d1[3] = v1.w;
        d2[0] = v2.x; d2[1] = v2.y; d2[2] = v2.z; d2[3] = v2.w;
    }

    const float* xb = x + b * D_ * N_;
    for (int idx = tid; idx < D_ * PR; idx += 256) {
        int d = idx >> 3, j = idx & 7;
        xs[idx] = xb[d * N_ + n0 + j];
    }
    __syncthreads();

    int a = tid;
    float acc1[PR], acc2[PR];
#pragma unroll
    for (int j = 0; j < PR; j++) { acc1[j] = 0.f; acc2[j] = 0.f; }

    const float* w1 = W1s + a * 97;
    const float* w2 = W2s + a * 97;
#pragma unroll 4
    for (int d = 0; d < D_; d++) {
        float wa = w1[d];
        float wb = w2[d];
        float4 x0 = *reinterpret_cast<const float4*>(xs + d * 8);
        float4 x1 = *reinterpret_cast<const float4*>(xs + d * 8 + 4);
        acc1[0] = fmaf(x0.x, wa, acc1[0]); acc2[0] = fmaf(x0.x, wb, acc2[0]);
        acc1[1] = fmaf(x0.y, wa, acc1[1]); acc2[1] = fmaf(x0.y, wb, acc2[1]);
        acc1[2] = fmaf(x0.z, wa, acc1[2]); acc2[2] = fmaf(x0.z, wb, acc2[2]);
        acc1[3] = fmaf(x0.w, wa, acc1[3]); acc2[3] = fmaf(x0.w, wb, acc2[3]);
        acc1[4] = fmaf(x1.x, wa, acc1[4]); acc2[4] = fmaf(x1.x, wb, acc2[4]);
        acc1[5] = fmaf(x1.y, wa, acc1[5]); acc2[5] = fmaf(x1.y, wb, acc2[5]);
        acc1[6] = fmaf(x1.z, wa, acc1[6]); acc2[6] = fmaf(x1.z, wb, acc2[6]);
        acc1[7] = fmaf(x1.w, wa, acc1[7]); acc2[7] = fmaf(x1.w, wb, acc2[7]);
    }

    float bgv = bg[a];
#pragma unroll
    for (int j = 0; j < PR; j++) {
        int row = b * N_ + n0 + j;
        g_G1h[row * ATTN_ + a] = __float2half_rn(acc1[j]);
        g_G2h[row * ATTN_ + a] = __float2half_rn(acc2[j] + bgv);
    }
}

// ---------------------------------------------------------------------------
// Kernel 2: lightly-persistent fused pairwise tanh (f16x2) + sigmoid + matmul.
// grid = 592 = 4 * 148 blocks (EVERY SM gets exactly 4 blocks, single wave),
// 256 threads (8 warps), R13 warp layout: pair p = w&3, a-half g = w>>2.
// Work items: 4096 = (b, n-tile of 8) x (m-tile of 32); block k statically
// handles the contiguous chunk [k*4096/592, (k+1)*4096/592) -> 6-7 items,
// worst-SM/avg = 28/27.68 = 1.012 (vs 1.16 with 512 blocks).
// Contiguous chunks keep n-tile runs: G1 restage + output flush only on
// n-tile change (1-2x per block); outputs accumulate in registers between.
// ---------------------------------------------------------------------------
#define MT 32
#define NITEMS 4096
#define NBLK   592

// byte offsets into dynamic smem (R13 layout)
#define OFFB_G1H  0                     // 8*256*2  = 4096
#define OFFB_ATT  4096                  // 8*33*4   = 1056
#define OFFB_ZB   5152                  // 8*32*4   = 1024
#define OFFB_G2H  6176                  // 32*264*2 = 16896
#define OFFB_XS   23072                 // 32*97*4  = 12416
#define SMEM_BYTES 35488                // 4 blocks/SM

#define KSTEP(Av, Bvv, Cv, Wv, A0, A1) {                     \
    __half2 g2h = U2H(Cv);                                   \
    __half2 w2  = U2H(Wv);                                   \
    __half2 t0  = tanh2(__hadd2(U2H(Av),  g2h));             \
    __half2 t1  = tanh2(__hadd2(U2H(Bvv), g2h));             \
    A0 = __hfma2(t0, w2, A0);                                \
    A1 = __hfma2(t1, w2, A1); }

__global__ __launch_bounds__(256, 4) void attn_kernel(
        const float* __restrict__ x,
        const float* __restrict__ Wa_b,
        const float* __restrict__ ba,
        float* __restrict__ out) {
    extern __shared__ char smc[];
    __half* G1s   = reinterpret_cast<__half*>(smc + OFFB_G1H);   // [8][256]
    float*  att_s = reinterpret_cast<float*>(smc + OFFB_ATT);    // [8][33]
    float*  zbuf  = reinterpret_cast<float*>(smc + OFFB_ZB);     // [8][32]
    __half* G2s   = reinterpret_cast<__half*>(smc + OFFB_G2H);   // [m][264]
    float*  xs    = reinterpret_cast<float*>(smc + OFFB_XS);     // [m][97]

    int blk = blockIdx.x;
    int it0 = (blk * NITEMS) / NBLK;          // = blk*256/37
    int it1 = ((blk + 1) * NITEMS) / NBLK;
    int tid = threadIdx.x;
    int w   = tid >> 5, l = tid & 31;
    int p   = w & 3;               // n-pair 0..3
    int g   = w >> 2;              // a-half 0/1

    float bias = Wa_b[0] + ba[0];

    float o00 = 0.f, o01 = 0.f, o02 = 0.f;
    float o10 = 0.f, o11 = 0.f, o12 = 0.f;
    int cur_nt = -1;

    const __half* g1r0 = G1s + (p << 1) * ATTN_;
    const __half* g1r1 = g1r0 + ATTN_;
    const __half* g2l  = G2s + l * 264;
    const float*  ar0  = att_s + (p << 1) * 33;
    const uint4*  wq   = reinterpret_cast<const uint4*>(c_wsh);

    for (int it = it0; it < it1; it++) {
        int nt = it >> 4;          // global n-tile id 0..255 (nt = b*64 + tile)
        int mt = it & 15;
        int m0 = mt << 5;
        int b  = nt >> 6;
        bool newnt = (nt != cur_nt);

        // Flush accumulated output rows on n-tile change (registers -> gmem).
        if (newnt && cur_nt >= 0) {
            float* op0 = out + (cur_nt * 8 + (p << 1)) * D_;
            float* op1 = op0 + D_;
            atomicAdd(op0 + l,      o00);
            atomicAdd(op0 + l + 32, o01);
            atomicAdd(op0 + l + 64, o02);
            atomicAdd(op1 + l,      o10);
            atomicAdd(op1 + l + 32, o11);
            atomicAdd(op1 + l + 64, o12);
            o00 = o01 = o02 = 0.f;
            o10 = o11 = o12 = 0.f;
        }

        __syncthreads();  // A: prev item's readers of G2s/xs/att_s (and G1s) done

        if (newnt) {
            // Stage G1 tile for this n-tile: 8*256 halves = 256 uint4.
            const uint4* src = reinterpret_cast<const uint4*>(
                                   g_G1h + nt * 8 * ATTN_);
            reinterpret_cast<uint4*>(smc + OFFB_G1H)[tid] = src[tid];
            cur_nt = nt;
        }
        // Stage G2 tile [m][264] halves (rows 528B; LDS.128 phases CF)
        {
            const uint4* g2g = reinterpret_cast<const uint4*>(
                                   g_G2h + (b * N_ + m0) * ATTN_);
            for (int idx = tid; idx < 1024; idx += 256) {
                int m = idx >> 5, c = idx & 31;
                *(reinterpret_cast<uint4*>(G2s + m * 264) + c) = g2g[idx];
            }
        }
        // x tile [m][97] f32 (global coalesced over m, smem stores CF)
        {
            const float* xb = x + b * D_ * N_;
            for (int idx = tid; idx < MT * D_; idx += 256) {
                int m = idx & 31, d = idx >> 5;
                xs[m * 97 + d] = xb[d * N_ + m0 + m];
            }
        }
        __syncthreads();  // B: tiles staged

        // Hot loop: this warp's 128-a half, both n of the pair, half2 math.
        float zf0 = 0.f, zf1 = 0.f;
#pragma unroll 1
        for (int c = 0; c < 4; c++) {
            int ah = (g << 7) + (c << 5);            // half-index base, 32 a
            __half2 a00 = __float2half2_rn(0.f), a01 = a00;
            __half2 a10 = a00, a11 = a00;
#pragma unroll 2
            for (int s = 0; s < 4; s++) {
                int off = ah + (s << 3);             // 8 a
                uint4 C = *reinterpret_cast<const uint4*>(g2l + off);
                uint4 W = wq[off >> 3];              // const port
                uint4 A  = *reinterpret_cast<const uint4*>(g1r0 + off);
                uint4 Bv = *reinterpret_cast<const uint4*>(g1r1 + off);
                KSTEP(A.x, Bv.x, C.x, W.x, a00, a10);
                KSTEP(A.y, Bv.y, C.y, W.y, a01, a11);
                KSTEP(A.z, Bv.z, C.z, W.z, a00, a10);
                KSTEP(A.w, Bv.w, C.w, W.w, a01, a11);
            }
            // Flush to fp32 (bounds f16 accumulation error)
            float2 f;
            f = __half22float2(a00); zf0 += f.x + f.y;
            f = __half22float2(a01); zf0 += f.x + f.y;
            f = __half22float2(a10); zf1 += f.x + f.y;
            f = __half22float2(a11); zf1 += f.x + f.y;
        }

        // a-half partial exchange: g=1 hands partials to g=0.
        if (g == 1) {
            zbuf[(p << 1) * 32 + l]       = zf0;
            zbuf[((p << 1) + 1) * 32 + l] = zf1;
        }
        __syncthreads();  // C: partials visible

        if (g == 0) {
            float z0 = zf0 + zbuf[(p << 1) * 32 + l];
            float z1 = zf1 + zbuf[((p << 1) + 1) * 32 + l];
            att_s[(p << 1) * 33 + l]       = 1.0f / (1.0f + __expf(-(z0 + bias)));
            att_s[((p << 1) + 1) * 33 + l] = 1.0f / (1.0f + __expf(-(z1 + bias)));
        }
        __syncthreads();  // D: att visible

        // Epilogue: group g covers m in [16g,16g+16); paired n shares xs loads.
#pragma unroll 4
        for (int mm = 0; mm < 16; mm++) {
            int mli = (g << 4) + mm;
            float av0 = ar0[mli];
            float av1 = ar0[33 + mli];
            const float* xr = xs + mli * 97;
            float x0 = xr[l];
            float x1 = xr[l + 32];
            float x2 = xr[l + 64];
            o00 = fmaf(av0, x0, o00);
            o01 = fmaf(av0, x1, o01);
            o02 = fmaf(av0, x2, o02);
            o10 = fmaf(av1, x0, o10);
            o11 = fmaf(av1, x1, o11);
            o12 = fmaf(av1, x2, o12);
        }
    }

    // Final flush (cur_nt >= 0: every block has >= 6 items).
    {
        float* op0 = out + (cur_nt * 8 + (p << 1)) * D_;
        float* op1 = op0 + D_;
        atomicAdd(op0 + l,      o00);
        atomicAdd(op0 + l + 32, o01);
        atomicAdd(op0 + l + 64, o02);
        atomicAdd(op1 + l,      o10);
        atomicAdd(op1 + l + 32, o11);
        atomicAdd(op1 + l + 64, o12);
    }
}

// ---------------------------------------------------------------------------
extern "C" void kernel_launch(void* const* d_in, const int* in_sizes, int n_in,
                              void* d_out, int out_size) {
    const float* x    = (const float*)d_in[0];
    const float* Wg1  = (const float*)d_in[1];
    const float* Wg2  = (const float*)d_in[2];
    const float* bg   = (const float*)d_in[3];
    const float* Wa_w = (const float*)d_in[4];
    const float* Wa_b = (const float*)d_in[5];
    const float* ba   = (const float*)d_in[6];
    float* out = (float*)d_out;

    int proj_smem = (2 * 256 * 97 + D_ * PR) * (int)sizeof(float);
    cudaFuncSetAttribute(proj_kernel,
                         cudaFuncAttributeMaxDynamicSharedMemorySize, proj_smem);
    proj_kernel<<<(B_ * N_) / PR, 256, proj_smem>>>(x, Wg1, Wg2, bg, Wa_w, out);

    // Packed half2 weights -> constant memory (in-stream after proj; D2D).
    void* wsp = nullptr;
    cudaGetSymbolAddress(&wsp, g_wsh);
    cudaMemcpyToSymbolAsync(c_wsh, wsp, (ATTN_ / 2) * sizeof(__half2), 0,
                            cudaMemcpyDeviceToDevice);

    cudaFuncSetAttribute(attn_kernel,
                         cudaFuncAttributeMaxDynamicSharedMemorySize, SMEM_BYTES);
    attn_kernel<<<NBLK, 256, SMEM_BYTES>>>(x, Wa_b, ba, out);
}